// round 2
// baseline (speedup 1.0000x reference)
#include <cuda_runtime.h>
#include <cstdint>

// Problem constants (fixed shapes per reference)
#define H_DIM   4096
#define R_DIM   16
#define N_TOK   32768          // B*S = 16*2048
#define TOK_PER_EXPERT 4096    // seg*S = 2*2048
#define TB      4              // tokens per block (token blocking for weight reuse)
#define NTHREADS 256

__device__ float g_mid[N_TOK * R_DIM];   // 2 MB scratch (static, allowed)

// keep-scale = SCALING / (1 - P_DROP), rounded exactly like f32(2.0/0.95)
#define KSCALE ((float)(2.0 / 0.95))
#define PDROP  0.05f

// ---------------------------------------------------------------------------
// Kernel 1: mid[g][r] = sum_h dropped(g,h) * A[e][r][h]
// Block handles TB=4 consecutive tokens (same expert since 4096 % 4 == 0).
// Each thread strides H with float4; A float4 load shared across 4 tokens.
// ---------------------------------------------------------------------------
__global__ __launch_bounds__(NTHREADS, 2)
void lora_mid_kernel(const float* __restrict__ data,
                     const float* __restrict__ mask,
                     const float* __restrict__ lora_a)
{
    const int tid = threadIdx.x;
    const int g0  = blockIdx.x * TB;
    const int e   = g0 >> 12;                 // g0 / TOK_PER_EXPERT
    const float* aBase = lora_a + (size_t)e * (R_DIM * H_DIM);

    float acc[TB][R_DIM];
#pragma unroll
    for (int t = 0; t < TB; t++)
#pragma unroll
        for (int r = 0; r < R_DIM; r++) acc[t][r] = 0.f;

#pragma unroll
    for (int it = 0; it < H_DIM / (4 * NTHREADS); it++) {
        const int h4 = (it * NTHREADS + tid) * 4;

        float4 dr[TB];
#pragma unroll
        for (int t = 0; t < TB; t++) {
            const size_t off = (size_t)(g0 + t) * H_DIM + h4;
            float4 x = *(const float4*)(data + off);
            float4 m = *(const float4*)(mask + off);
            dr[t].x = (m.x >= PDROP) ? x.x * KSCALE : 0.f;
            dr[t].y = (m.y >= PDROP) ? x.y * KSCALE : 0.f;
            dr[t].z = (m.z >= PDROP) ? x.z * KSCALE : 0.f;
            dr[t].w = (m.w >= PDROP) ? x.w * KSCALE : 0.f;
        }

#pragma unroll
        for (int r = 0; r < R_DIM; r++) {
            const float4 a4 = *(const float4*)(aBase + r * H_DIM + h4);
#pragma unroll
            for (int t = 0; t < TB; t++) {
                acc[t][r] += dr[t].x * a4.x + dr[t].y * a4.y
                           + dr[t].z * a4.z + dr[t].w * a4.w;
            }
        }
    }

    // Intra-warp butterfly reduction (all 64 accumulators)
#pragma unroll
    for (int t = 0; t < TB; t++)
#pragma unroll
        for (int r = 0; r < R_DIM; r++) {
#pragma unroll
            for (int off = 16; off > 0; off >>= 1)
                acc[t][r] += __shfl_xor_sync(0xffffffffu, acc[t][r], off);
        }

    // Cross-warp via smem: 8 warps x 64 values
    __shared__ float red[8][TB * R_DIM];
    const int wid  = tid >> 5;
    const int lane = tid & 31;
    if (lane == 0) {
#pragma unroll
        for (int t = 0; t < TB; t++)
#pragma unroll
            for (int r = 0; r < R_DIM; r++)
                red[wid][t * R_DIM + r] = acc[t][r];
    }
    __syncthreads();

    if (tid < TB * R_DIM) {
        float s = 0.f;
#pragma unroll
        for (int w = 0; w < 8; w++) s += red[w][tid];
        const int t = tid >> 4;
        const int r = tid & 15;
        g_mid[(size_t)(g0 + t) * R_DIM + r] = s;
    }
}

// ---------------------------------------------------------------------------
// Kernel 2: out[g][h] = result[g][h] + sum_r mid[g][r] * B[e][h][r]
// Block handles TB=4 tokens; mid kept in 64 registers; B row = 16 contiguous
// floats -> 4x LDG.128 per h, reused across the 4 tokens.
// ---------------------------------------------------------------------------
__global__ __launch_bounds__(NTHREADS, 2)
void lora_out_kernel(const float* __restrict__ result,
                     const float* __restrict__ lora_b,
                     float* __restrict__ out)
{
    const int tid = threadIdx.x;
    const int g0  = blockIdx.x * TB;
    const int e   = g0 >> 12;
    const float* bBase = lora_b + (size_t)e * (H_DIM * R_DIM);

    float mid[TB][R_DIM];
#pragma unroll
    for (int t = 0; t < TB; t++) {
        const float4* mp = (const float4*)(g_mid + (size_t)(g0 + t) * R_DIM);
#pragma unroll
        for (int q = 0; q < 4; q++) {
            float4 v = mp[q];
            mid[t][q * 4 + 0] = v.x;
            mid[t][q * 4 + 1] = v.y;
            mid[t][q * 4 + 2] = v.z;
            mid[t][q * 4 + 3] = v.w;
        }
    }

#pragma unroll 4
    for (int it = 0; it < H_DIM / NTHREADS; it++) {
        const int h = it * NTHREADS + tid;
        const float4* bw = (const float4*)(bBase + (size_t)h * R_DIM);
        const float4 b0 = bw[0], b1 = bw[1], b2 = bw[2], b3 = bw[3];

#pragma unroll
        for (int t = 0; t < TB; t++) {
            const size_t o = (size_t)(g0 + t) * H_DIM + h;
            float s = result[o];
            s += mid[t][0]  * b0.x + mid[t][1]  * b0.y
               + mid[t][2]  * b0.z + mid[t][3]  * b0.w;
            s += mid[t][4]  * b1.x + mid[t][5]  * b1.y
               + mid[t][6]  * b1.z + mid[t][7]  * b1.w;
            s += mid[t][8]  * b2.x + mid[t][9]  * b2.y
               + mid[t][10] * b2.z + mid[t][11] * b2.w;
            s += mid[t][12] * b3.x + mid[t][13] * b3.y
               + mid[t][14] * b3.z + mid[t][15] * b3.w;
            out[o] = s;
        }
    }
}

// ---------------------------------------------------------------------------
extern "C" void kernel_launch(void* const* d_in, const int* in_sizes, int n_in,
                              void* d_out, int out_size)
{
    const float* result   = (const float*)d_in[0];
    const float* data     = (const float*)d_in[1];
    const float* dropmask = (const float*)d_in[2];
    const float* lora_a   = (const float*)d_in[3];
    const float* lora_b   = (const float*)d_in[4];
    float* out = (float*)d_out;

    const int nblocks = N_TOK / TB;   // 8192
    lora_mid_kernel<<<nblocks, NTHREADS>>>(data, dropmask, lora_a);
    lora_out_kernel<<<nblocks, NTHREADS>>>(result, lora_b, out);
}